// round 5
// baseline (speedup 1.0000x reference)
#include <cuda_runtime.h>

// ---------------- problem dims ----------------
#define Bn 256
#define Sn 336
#define Fn 8
#define Hn 512
#define Pn 96

// ---------------- partition ----------------
#define GB   2                 // batch groups
#define GHN  64                // h-column groups
#define NBLK (GB * GHN)        // 128 blocks, 1 per SM
#define BT   128               // batches per block
#define CT   8                 // h-cols per block
#define NR   32                // gate rows per block (4 * CT)
#define KC   64                // k chunk
#define NCHUNK (Hn / KC)       // 8

// duplicated weight row: 1024 floats (each w twice) + pad so that
// consecutive rows start 4 banks apart (1028 % 32 == 4) -> 8 rows tile 32 banks
#define WSTRIDE2 1028
#define HSTRIDE (BT + 4)       // 132
#define HBUF    (KC * HSTRIDE) // floats per h_sh buffer

#define SMEM_FLOATS (NR * WSTRIDE2 + 2 * HBUF + BT * Fn + NR + NR * Fn)
#define SMEM_BYTES  (SMEM_FLOATS * 4)

// ---------------- device scratch ----------------
__device__ float    g_h[2][Hn][Bn];   // ping-pong h state, stored [col][batch]
__device__ unsigned g_bar_count;
__device__ unsigned g_bar_gen;

// ---------------- helpers ----------------
__device__ __forceinline__ void cp_async16(void* dst_sh, const void* src) {
    unsigned d = (unsigned)__cvta_generic_to_shared(dst_sh);
    asm volatile("cp.async.ca.shared.global [%0], [%1], 16;\n" :: "r"(d), "l"(src));
}
__device__ __forceinline__ void cp_commit() {
    asm volatile("cp.async.commit_group;\n" ::: "memory");
}
template <int N>
__device__ __forceinline__ void cp_wait() {
    asm volatile("cp.async.wait_group %0;\n" :: "n"(N) : "memory");
}

__device__ __forceinline__ float sigf(float x) {
    return 1.0f / (1.0f + __expf(-x));
}
__device__ __forceinline__ float tanh_fast(float x) {
    return 2.0f / (1.0f + __expf(-2.0f * x)) - 1.0f;
}

// packed fp32x2 FMA: d = a*b + d (each operand is a pair of fp32 in a b64 reg)
__device__ __forceinline__ void fma2(unsigned long long& d,
                                     unsigned long long a,
                                     unsigned long long b) {
    asm("fma.rn.f32x2 %0, %1, %2, %0;" : "+l"(d) : "l"(a), "l"(b));
}
__device__ __forceinline__ unsigned long long pack2(float lo, float hi) {
    unsigned long long r;
    asm("mov.b64 %0, {%1, %2};" : "=l"(r) : "f"(lo), "f"(hi));
    return r;
}
__device__ __forceinline__ void unpack2(unsigned long long v, float& lo, float& hi) {
    asm("mov.b64 {%0, %1}, %2;" : "=f"(lo), "=f"(hi) : "l"(v));
}

// grid-wide barrier, acquire/release (no membar.gpu)
__device__ __forceinline__ void grid_barrier() {
    __syncthreads();
    if (threadIdx.x == 0) {
        unsigned gen;
        asm volatile("ld.acquire.gpu.u32 %0, [%1];"
                     : "=r"(gen) : "l"(&g_bar_gen) : "memory");
        unsigned prev;
        asm volatile("atom.add.release.gpu.u32 %0, [%1], 1;"
                     : "=r"(prev) : "l"(&g_bar_count) : "memory");
        if (prev == NBLK - 1) {
            asm volatile("st.relaxed.gpu.u32 [%0], %1;"
                         :: "l"(&g_bar_count), "r"(0u) : "memory");
            asm volatile("st.release.gpu.u32 [%0], %1;"
                         :: "l"(&g_bar_gen), "r"(gen + 1u) : "memory");
        } else {
            unsigned cur;
            do {
                asm volatile("ld.acquire.gpu.u32 %0, [%1];"
                             : "=r"(cur) : "l"(&g_bar_gen) : "memory");
            } while (cur == gen);
        }
    }
    __syncthreads();
}

// stage a 32-row x 512-col weight slice into smem, duplicating every element:
// row layout [w0,w0,w1,w1,...,w511,w511] (+4 pad floats)
__device__ __forceinline__ void stage_weights_dup(float* w_sh, const float* W,
                                                  int colbase, int tid) {
    const int r    = tid >> 3;       // local row 0..31
    const int seg  = tid & 7;        // 64-float source segment
    const int gate = r >> 3;
    const int cc   = r & 7;
    const float* src = W + (size_t)(gate * Hn + colbase + cc) * Hn + seg * 64;
    float*       dst = w_sh + r * WSTRIDE2 + seg * 128;
    #pragma unroll
    for (int j = 0; j < 16; j++) {
        const float4 v = ((const float4*)src)[j];
        ((float4*)dst)[2 * j]     = make_float4(v.x, v.x, v.y, v.y);
        ((float4*)dst)[2 * j + 1] = make_float4(v.z, v.z, v.w, v.w);
    }
}

// ---------------- kernel ----------------
__global__ void __launch_bounds__(256, 1)
lstm_kernel(const float* __restrict__ x_enc,
            const float* __restrict__ enc_Wih,
            const float* __restrict__ enc_Whh,
            const float* __restrict__ enc_b,
            const float* __restrict__ dec_Wih,
            const float* __restrict__ dec_Whh,
            const float* __restrict__ dec_b,
            const float* __restrict__ lin_W,
            const float* __restrict__ lin_b,
            float* __restrict__ out)
{
    extern __shared__ float smem[];
    float* w_sh    = smem;                        // [NR][WSTRIDE2] duplicated
    float* h_sh    = w_sh + NR * WSTRIDE2;        // [2][KC][HSTRIDE]
    float* x_sh    = h_sh + 2 * HBUF;             // [BT][Fn]
    float* bias_sh = x_sh + BT * Fn;              // [NR]
    float* wih_sh  = bias_sh + NR;                // [NR][Fn] (enc) / [NR] (dec)

    const int tid     = threadIdx.x;
    const int bid     = blockIdx.x;
    const int gh      = bid % GHN;
    const int gbx     = bid / GHN;
    const int bstart  = gbx * BT;
    const int colbase = gh * CT;

    const int c   = tid & 7;    // col within group (0..7)
    const int bq  = tid >> 3;   // batch quad (0..31)
    const int bl0 = bq * 4;     // local batch base

    // ---- stage encoder weights (duplicated) + bias + Wih ----
    stage_weights_dup(w_sh, enc_Whh, colbase, tid);
    if (tid < NR) {
        const int g2 = tid >> 3, c2 = tid & 7;
        bias_sh[tid] = enc_b[g2 * Hn + colbase + c2];
        #pragma unroll
        for (int k = 0; k < Fn; k++)
            wih_sh[tid * Fn + k] = enc_Wih[(size_t)(g2 * Hn + colbase + c2) * Fn + k];
    }

    // ---- per-launch re-init of global scratch ----
    {
        float* z = &g_h[1][0][0] + bid * ((Hn * Bn) / NBLK);
        for (int j = tid; j < (Hn * Bn) / NBLK; j += 256) z[j] = 0.0f;
        const int per  = (Bn * Pn + NBLK - 1) / NBLK;
        const int base = bid * per;
        for (int j = tid; j < per; j += 256)
            if (base + j < Bn * Pn) out[base + j] = 0.0f;
    }

    float creg[4] = {0.f, 0.f, 0.f, 0.f};
    const float lw = lin_W[colbase + c];
    const float lb = lin_b[0];

    grid_barrier();

    for (int s = 0; s < Sn + Pn; s++) {
        const bool enc = (s < Sn);
        const float* hprev = &g_h[(s + 1) & 1][0][0];
        float*       hnext = &g_h[s & 1][0][0];

        // ---- encoder -> decoder weight swap (once) ----
        if (s == Sn) {
            __syncthreads();
            stage_weights_dup(w_sh, dec_Whh, colbase, tid);
            if (tid < NR) {
                const int g2 = tid >> 3, c2 = tid & 7;
                bias_sh[tid] = dec_b[g2 * Hn + colbase + c2];
                wih_sh[tid]  = dec_Wih[g2 * Hn + colbase + c2];
            }
            __syncthreads();
        }

        // ---- init accumulators: bias + input term (scalar), then pack ----
        float acc[4][4];
        if (enc) {
            {
                const int b = tid >> 1, part = tid & 1;
                const float4 v = *(const float4*)(x_enc +
                        ((size_t)(bstart + b) * Sn + s) * Fn + part * 4);
                *((float4*)&x_sh[b * Fn + part * 4]) = v;
            }
            __syncthreads();
            #pragma unroll
            for (int i = 0; i < 4; i++) {
                #pragma unroll
                for (int g2 = 0; g2 < 4; g2++) {
                    float a = bias_sh[g2 * 8 + c];
                    #pragma unroll
                    for (int k = 0; k < Fn; k++)
                        a = fmaf(x_sh[(bl0 + i) * Fn + k], wih_sh[(g2 * 8 + c) * Fn + k], a);
                    acc[i][g2] = a;
                }
            }
        } else {
            float xv[4];
            #pragma unroll
            for (int i = 0; i < 4; i++) {
                const int b = bstart + bl0 + i;
                xv[i] = (s == Sn) ? x_enc[((size_t)b * Sn + (Sn - 1)) * Fn + 3]
                                  : out[(size_t)b * Pn + (s - Sn - 1)];
            }
            #pragma unroll
            for (int i = 0; i < 4; i++)
                #pragma unroll
                for (int g2 = 0; g2 < 4; g2++)
                    acc[i][g2] = fmaf(xv[i], wih_sh[g2 * 8 + c], bias_sh[g2 * 8 + c]);
        }

        // pack accumulators into f32x2 pairs: p=0 -> (b0,b1), p=1 -> (b2,b3)
        unsigned long long acc2[2][4];
        #pragma unroll
        for (int g2 = 0; g2 < 4; g2++) {
            acc2[0][g2] = pack2(acc[0][g2], acc[1][g2]);
            acc2[1][g2] = pack2(acc[2][g2], acc[3][g2]);
        }

        // ---- GEMM over K=512, cp.async double-buffered h chunks ----
        {
            #pragma unroll
            for (int j = 0; j < 8; j++) {
                const int idx = j * 256 + tid;
                const int row = idx >> 5;
                const int q   = idx & 31;
                cp_async16(h_sh + row * HSTRIDE + q * 4,
                           hprev + (size_t)row * Bn + bstart + q * 4);
            }
            cp_commit();
        }

        for (int ci = 0; ci < NCHUNK; ci++) {
            const int kc = ci * KC;
            __syncthreads();
            if (ci + 1 < NCHUNK) {
                float* dst = h_sh + ((ci + 1) & 1) * HBUF;
                const float* srcb = hprev + (size_t)(kc + KC) * Bn + bstart;
                #pragma unroll
                for (int j = 0; j < 8; j++) {
                    const int idx = j * 256 + tid;
                    const int row = idx >> 5;
                    const int q   = idx & 31;
                    cp_async16(dst + row * HSTRIDE + q * 4, srcb + (size_t)row * Bn + q * 4);
                }
                cp_commit();
                cp_wait<1>();
            } else {
                cp_wait<0>();
            }
            __syncthreads();

            const float* hS = h_sh + (ci & 1) * HBUF;
            #pragma unroll 4
            for (int k = 0; k < KC; k += 4) {
                // h pairs: hp[k'] = ((h[k'][b0],h[k'][b1]), (h[k'][b2],h[k'][b3]))
                const ulonglong2 hp0 = *(const ulonglong2*)(hS + (k + 0) * HSTRIDE + bl0);
                const ulonglong2 hp1 = *(const ulonglong2*)(hS + (k + 1) * HSTRIDE + bl0);
                const ulonglong2 hp2 = *(const ulonglong2*)(hS + (k + 2) * HSTRIDE + bl0);
                const ulonglong2 hp3 = *(const ulonglong2*)(hS + (k + 3) * HSTRIDE + bl0);
                #pragma unroll
                for (int g2 = 0; g2 < 4; g2++) {
                    const float* wr = w_sh + (g2 * 8 + c) * WSTRIDE2 + 2 * (kc + k);
                    // duplicated row: float offsets 0..3 = (wk0,wk0,wk1,wk1),
                    //                 float offsets 4..7 = (wk2,wk2,wk3,wk3)
                    const ulonglong2 w01 = *(const ulonglong2*)(wr);
                    const ulonglong2 w23 = *(const ulonglong2*)(wr + 4);
                    fma2(acc2[0][g2], hp0.x, w01.x);
                    fma2(acc2[1][g2], hp0.y, w01.x);
                    fma2(acc2[0][g2], hp1.x, w01.y);
                    fma2(acc2[1][g2], hp1.y, w01.y);
                    fma2(acc2[0][g2], hp2.x, w23.x);
                    fma2(acc2[1][g2], hp2.y, w23.x);
                    fma2(acc2[0][g2], hp3.x, w23.y);
                    fma2(acc2[1][g2], hp3.y, w23.y);
                }
            }
        }

        // unpack accumulators
        #pragma unroll
        for (int g2 = 0; g2 < 4; g2++) {
            unpack2(acc2[0][g2], acc[0][g2], acc[1][g2]);
            unpack2(acc2[1][g2], acc[2][g2], acc[3][g2]);
        }

        // ---- activations, state update, h write ----
        float hnew[4];
        #pragma unroll
        for (int i = 0; i < 4; i++) {
            const float ig = sigf(acc[i][0]);
            const float fg = sigf(acc[i][1]);
            const float gg = tanh_fast(acc[i][2]);
            const float og = sigf(acc[i][3]);
            const float cn = fmaf(fg, creg[i], ig * gg);
            creg[i] = cn;
            hnew[i] = og * tanh_fast(cn);
            hnext[(size_t)(colbase + c) * Bn + (bstart + bl0 + i)] = hnew[i];
        }

        // ---- decoder output ----
        if (!enc) {
            float py[4];
            #pragma unroll
            for (int i = 0; i < 4; i++) py[i] = hnew[i] * lw;
            #pragma unroll
            for (int off = 4; off >= 1; off >>= 1) {
                #pragma unroll
                for (int i = 0; i < 4; i++)
                    py[i] += __shfl_down_sync(0xffffffffu, py[i], off, 8);
            }
            if (c == 0) {
                const float add = (gh == 0) ? lb : 0.0f;
                #pragma unroll
                for (int i = 0; i < 4; i++)
                    atomicAdd(&out[(size_t)(bstart + bl0 + i) * Pn + (s - Sn)], py[i] + add);
            }
        }

        grid_barrier();
    }
}

// ---------------- launch ----------------
extern "C" void kernel_launch(void* const* d_in, const int* in_sizes, int n_in,
                              void* d_out, int out_size)
{
    const float* x_enc   = (const float*)d_in[0];
    const float* enc_Wih = (const float*)d_in[1];
    const float* enc_Whh = (const float*)d_in[2];
    const float* enc_b   = (const float*)d_in[3];
    const float* dec_Wih = (const float*)d_in[4];
    const float* dec_Whh = (const float*)d_in[5];
    const float* dec_b   = (const float*)d_in[6];
    const float* lin_W   = (const float*)d_in[7];
    const float* lin_b   = (const float*)d_in[8];
    float* out = (float*)d_out;

    cudaFuncSetAttribute(lstm_kernel,
                         cudaFuncAttributeMaxDynamicSharedMemorySize, SMEM_BYTES);

    lstm_kernel<<<NBLK, 256, SMEM_BYTES>>>(x_enc, enc_Wih, enc_Whh, enc_b,
                                           dec_Wih, dec_Whh, dec_b,
                                           lin_W, lin_b, out);
}

// round 6
// speedup vs baseline: 2.5799x; 2.5799x over previous
#include <cuda_runtime.h>
#include <cuda_bf16.h>

// ---------------- problem dims ----------------
#define Bn 256
#define Sn 336
#define Fn 8
#define Hn 512
#define Pn 96

// ---------------- partition ----------------
#define GB   2                 // batch halves
#define GHN  64                // col groups
#define NBLK (GB * GHN)        // 128 blocks
#define BT   128               // batches per block
#define CT   8                 // cols per block
#define NR   32                // gate rows per block
#define KCH  128               // k elements per chunk
#define NCH  (Hn / KCH)        // 4

// smem strides in u32 units (each u32 = packed bf16 hi<<16 | lo of one element)
#define WPS 520                // W row stride (512 + 8 pad -> rows start 8 u32-banks apart)
#define BPS 136                // h row stride (128 + 8 pad)

#define W_U32   (NR * WPS)             // 16640
#define B_U32   (BT * BPS)             // 17408 per buffer
#define SMEM_U32 (W_U32 + 2 * B_U32)   // 51456
#define XS_F    (BT * Fn)              // 1024
#define SMEM_BYTES ((SMEM_U32 + XS_F + NR + NR * Fn) * 4)

// ---------------- device scratch ----------------
__device__ unsigned g_h[2][Bn][Hn];    // packed bf16 hi/lo h state, [batch][col]
__device__ unsigned g_bar_count;
__device__ unsigned g_bar_gen;

// ---------------- helpers ----------------
__device__ __forceinline__ void cp_async16(void* dst_sh, const void* src) {
    unsigned d = (unsigned)__cvta_generic_to_shared(dst_sh);
    asm volatile("cp.async.ca.shared.global [%0], [%1], 16;\n" :: "r"(d), "l"(src));
}
__device__ __forceinline__ void cp_commit() {
    asm volatile("cp.async.commit_group;\n" ::: "memory");
}
template <int N>
__device__ __forceinline__ void cp_wait() {
    asm volatile("cp.async.wait_group %0;\n" :: "n"(N) : "memory");
}

__device__ __forceinline__ float sigf(float x) {
    return 1.0f / (1.0f + __expf(-x));
}
__device__ __forceinline__ float tanh_fast(float x) {
    return 2.0f / (1.0f + __expf(-2.0f * x)) - 1.0f;
}

// split fp32 into bf16 hi/lo, pack into u32 (hi in upper 16 bits)
__device__ __forceinline__ unsigned packsplit(float x) {
    __nv_bfloat16 h = __float2bfloat16(x);
    float xh = __bfloat162float(h);
    __nv_bfloat16 l = __float2bfloat16(x - xh);
    return ((unsigned)__bfloat16_as_ushort(h) << 16) |
            (unsigned)__bfloat16_as_ushort(l);
}

// m16n8k16 bf16 MMA, fp32 accumulate (D == C)
__device__ __forceinline__ void mma_bf16(float d[4], const unsigned a[4],
                                         const unsigned b0, const unsigned b1) {
    asm volatile(
        "mma.sync.aligned.m16n8k16.row.col.f32.bf16.bf16.f32 "
        "{%0,%1,%2,%3},{%4,%5,%6,%7},{%8,%9},{%0,%1,%2,%3};"
        : "+f"(d[0]), "+f"(d[1]), "+f"(d[2]), "+f"(d[3])
        : "r"(a[0]), "r"(a[1]), "r"(a[2]), "r"(a[3]), "r"(b0), "r"(b1));
}

// grid-wide barrier, acquire/release
__device__ __forceinline__ void grid_barrier() {
    __syncthreads();
    if (threadIdx.x == 0) {
        unsigned gen;
        asm volatile("ld.acquire.gpu.u32 %0, [%1];"
                     : "=r"(gen) : "l"(&g_bar_gen) : "memory");
        unsigned prev;
        asm volatile("atom.add.release.gpu.u32 %0, [%1], 1;"
                     : "=r"(prev) : "l"(&g_bar_count) : "memory");
        if (prev == NBLK - 1) {
            asm volatile("st.relaxed.gpu.u32 [%0], %1;"
                         :: "l"(&g_bar_count), "r"(0u) : "memory");
            asm volatile("st.release.gpu.u32 [%0], %1;"
                         :: "l"(&g_bar_gen), "r"(gen + 1u) : "memory");
        } else {
            unsigned cur;
            do {
                asm volatile("ld.acquire.gpu.u32 %0, [%1];"
                             : "=r"(cur) : "l"(&g_bar_gen) : "memory");
            } while (cur == gen);
        }
    }
    __syncthreads();
}

// stage 32x512 weight slice (rows = gate*8+cc), split-packed, into smem
__device__ __forceinline__ void stage_weights(unsigned* Wp, const float* W,
                                              int colbase, int tid) {
    const int r    = tid >> 3;      // 0..31
    const int seg  = tid & 7;       // 64-col segment
    const int gate = r >> 3;
    const int cc   = r & 7;
    const float* src = W + (size_t)(gate * Hn + colbase + cc) * Hn + seg * 64;
    unsigned*    dst = Wp + r * WPS + seg * 64;
    #pragma unroll
    for (int j = 0; j < 16; j++) {
        const float4 v = ((const float4*)src)[j];
        dst[4 * j + 0] = packsplit(v.x);
        dst[4 * j + 1] = packsplit(v.y);
        dst[4 * j + 2] = packsplit(v.z);
        dst[4 * j + 3] = packsplit(v.w);
    }
}

// ---------------- kernel ----------------
__global__ void __launch_bounds__(256, 1)
lstm_kernel(const float* __restrict__ x_enc,
            const float* __restrict__ enc_Wih,
            const float* __restrict__ enc_Whh,
            const float* __restrict__ enc_b,
            const float* __restrict__ dec_Wih,
            const float* __restrict__ dec_Whh,
            const float* __restrict__ dec_b,
            const float* __restrict__ lin_W,
            const float* __restrict__ lin_b,
            float* __restrict__ out)
{
    extern __shared__ unsigned smem_u[];
    unsigned* Wp   = smem_u;                 // [NR][WPS] packed weights
    unsigned* Bsh  = smem_u + W_U32;         // [2][BT][BPS] packed h chunks
    float* x_sh    = (float*)(smem_u + SMEM_U32);   // [BT][Fn]
    float* bias_sh = x_sh + XS_F;            // [NR]
    float* wih_sh  = bias_sh + NR;           // [NR][Fn] (enc) / [NR] (dec)

    const int tid     = threadIdx.x;
    const int bid     = blockIdx.x;
    const int gh      = bid % GHN;
    const int gbx     = bid / GHN;
    const int bstart  = gbx * BT;
    const int colbase = gh * CT;

    const int w    = tid >> 5;      // warp 0..7 (owns batches w*16..w*16+15)
    const int lane = tid & 31;
    const int cc   = lane >> 2;     // col within group 0..7 (also frag row/ncol id)
    const int q    = lane & 3;      // quad id: batch pair base 2q

    // ---- stage encoder weights + bias + Wih ----
    stage_weights(Wp, enc_Whh, colbase, tid);
    if (tid < NR) {
        const int g2 = tid >> 3, c2 = tid & 7;
        bias_sh[tid] = enc_b[g2 * Hn + colbase + c2];
        #pragma unroll
        for (int k = 0; k < Fn; k++)
            wih_sh[tid * Fn + k] = enc_Wih[(size_t)(g2 * Hn + colbase + c2) * Fn + k];
    }

    // ---- per-launch re-init of global scratch ----
    {
        unsigned* z = &g_h[1][0][0] + bid * ((Bn * Hn) / NBLK);
        for (int j = tid; j < (Bn * Hn) / NBLK; j += 256) z[j] = 0u;
        const int per  = (Bn * Pn + NBLK - 1) / NBLK;
        const int base = bid * per;
        for (int j = tid; j < per; j += 256)
            if (base + j < Bn * Pn) out[base + j] = 0.0f;
    }

    float creg[4] = {0.f, 0.f, 0.f, 0.f};   // c-state: (tn,j) -> idx 2*tn+j
    const float lw = lin_W[colbase + cc];
    const float lb = lin_b[0];
    float bias_r[4];
    #pragma unroll
    for (int g2 = 0; g2 < 4; g2++) bias_r[g2] = 0.0f;   // set after barrier

    grid_barrier();   // scratch zeroed, weights staged

    #pragma unroll
    for (int g2 = 0; g2 < 4; g2++) bias_r[g2] = bias_sh[g2 * 8 + cc];

    for (int s = 0; s < Sn + Pn; s++) {
        const bool enc = (s < Sn);
        const unsigned* hprev = &g_h[(s + 1) & 1][0][0];
        unsigned*       hnext = &g_h[s & 1][0][0];

        // ---- encoder -> decoder weight swap (once) ----
        if (s == Sn) {
            __syncthreads();
            stage_weights(Wp, dec_Whh, colbase, tid);
            if (tid < NR) {
                const int g2 = tid >> 3, c2 = tid & 7;
                bias_sh[tid] = dec_b[g2 * Hn + colbase + c2];
                wih_sh[tid]  = dec_Wih[g2 * Hn + colbase + c2];
            }
            __syncthreads();
            #pragma unroll
            for (int g2 = 0; g2 < 4; g2++) bias_r[g2] = bias_sh[g2 * 8 + cc];
        }

        // ---- accumulator init: bias + Wih*x ----
        // d[tm][tn][j]: tm0 -> gates 0(i),1(f); tm1 -> gates 2(g),3(o)
        //   regs {0,1} = gate 2tm,   batches (tn*8+2q, +1)
        //   regs {2,3} = gate 2tm+1, same batches
        float d[2][2][4];
        if (enc) {
            {   // stage x_t tile: 128 batches x 8 feats
                const int b = tid >> 1, part = tid & 1;
                const float4 v = *(const float4*)(x_enc +
                        ((size_t)(bstart + b) * Sn + s) * Fn + part * 4);
                *((float4*)&x_sh[b * Fn + part * 4]) = v;
            }
            __syncthreads();
            #pragma unroll
            for (int tn = 0; tn < 2; tn++) {
                #pragma unroll
                for (int j = 0; j < 2; j++) {
                    const int nb = w * 16 + tn * 8 + 2 * q + j;
                    float t[4];
                    #pragma unroll
                    for (int g2 = 0; g2 < 4; g2++) t[g2] = bias_r[g2];
                    #pragma unroll
                    for (int k = 0; k < Fn; k++) {
                        const float xv = x_sh[nb * Fn + k];
                        #pragma unroll
                        for (int g2 = 0; g2 < 4; g2++)
                            t[g2] = fmaf(xv, wih_sh[(g2 * 8 + cc) * Fn + k], t[g2]);
                    }
                    d[0][tn][0 + j] = t[0];  // gate 0 (i)
                    d[0][tn][2 + j] = t[1];  // gate 1 (f)
                    d[1][tn][0 + j] = t[2];  // gate 2 (g)
                    d[1][tn][2 + j] = t[3];  // gate 3 (o)
                }
            }
        } else {
            float wv[4];
            #pragma unroll
            for (int g2 = 0; g2 < 4; g2++) wv[g2] = wih_sh[g2 * 8 + cc];
            #pragma unroll
            for (int tn = 0; tn < 2; tn++) {
                #pragma unroll
                for (int j = 0; j < 2; j++) {
                    const int b = bstart + w * 16 + tn * 8 + 2 * q + j;
                    const float xv = (s == Sn)
                        ? x_enc[((size_t)b * Sn + (Sn - 1)) * Fn + 3]
                        : out[(size_t)b * Pn + (s - Sn - 1)];
                    d[0][tn][0 + j] = fmaf(xv, wv[0], bias_r[0]);
                    d[0][tn][2 + j] = fmaf(xv, wv[1], bias_r[1]);
                    d[1][tn][0 + j] = fmaf(xv, wv[2], bias_r[2]);
                    d[1][tn][2 + j] = fmaf(xv, wv[3], bias_r[3]);
                }
            }
        }

        // ---- GEMM over K=512, cp.async double-buffered packed-h chunks ----
        {   // prefetch chunk 0: 128 rows x 128 u32 (512B/row)
            #pragma unroll
            for (int j = 0; j < 16; j++) {
                const int idx = j * 256 + tid;     // 4096 x 16B
                const int row = idx >> 5;
                const int qq  = idx & 31;
                cp_async16(Bsh + row * BPS + qq * 4,
                           hprev + (size_t)(bstart + row) * Hn + qq * 4);
            }
            cp_commit();
        }

        for (int ci = 0; ci < NCH; ci++) {
            __syncthreads();
            if (ci + 1 < NCH) {
                unsigned* dst = Bsh + ((ci + 1) & 1) * B_U32;
                const unsigned* srcb = hprev + (size_t)bstart * Hn + (ci + 1) * KCH;
                #pragma unroll
                for (int j = 0; j < 16; j++) {
                    const int idx = j * 256 + tid;
                    const int row = idx >> 5;
                    const int qq  = idx & 31;
                    cp_async16(dst + row * BPS + qq * 4,
                               srcb + (size_t)row * Hn + qq * 4);
                }
                cp_commit();
                cp_wait<1>();
            } else {
                cp_wait<0>();
            }
            __syncthreads();

            const unsigned* Bc = Bsh + (ci & 1) * B_U32;
            #pragma unroll
            for (int kt = 0; kt < KCH / 16; kt++) {        // 8 k16 steps
                const int kA = ci * KCH + kt * 16;          // global k (u32 idx)
                const int kB = kt * 16;                     // chunk-local

                // A fragments (rows = gate rows), both M-tiles, hi+lo
                unsigned a_hi[2][4], a_lo[2][4];
                #pragma unroll
                for (int tm = 0; tm < 2; tm++) {
                    const unsigned* r0 = Wp + (16 * tm + cc) * WPS + kA + 2 * q;
                    const unsigned* r1 = r0 + 8 * WPS;      // row +8
                    const uint2 p0 = *(const uint2*)(r0);       // k pair 2q
                    const uint2 p1 = *(const uint2*)(r1);
                    const uint2 p2 = *(const uint2*)(r0 + 8);   // k pair 2q+8
                    const uint2 p3 = *(const uint2*)(r1 + 8);
                    a_hi[tm][0] = __byte_perm(p0.x, p0.y, 0x7632);
                    a_hi[tm][1] = __byte_perm(p1.x, p1.y, 0x7632);
                    a_hi[tm][2] = __byte_perm(p2.x, p2.y, 0x7632);
                    a_hi[tm][3] = __byte_perm(p3.x, p3.y, 0x7632);
                    a_lo[tm][0] = __byte_perm(p0.x, p0.y, 0x5410);
                    a_lo[tm][1] = __byte_perm(p1.x, p1.y, 0x5410);
                    a_lo[tm][2] = __byte_perm(p2.x, p2.y, 0x5410);
                    a_lo[tm][3] = __byte_perm(p3.x, p3.y, 0x5410);
                }
                // B fragments (n = batch), both N-tiles, hi+lo
                unsigned b_hi[2][2], b_lo[2][2];
                #pragma unroll
                for (int tn = 0; tn < 2; tn++) {
                    const unsigned* br = Bc + (w * 16 + tn * 8 + cc) * BPS + kB + 2 * q;
                    const uint2 p0 = *(const uint2*)(br);
                    const uint2 p1 = *(const uint2*)(br + 8);
                    b_hi[tn][0] = __byte_perm(p0.x, p0.y, 0x7632);
                    b_hi[tn][1] = __byte_perm(p1.x, p1.y, 0x7632);
                    b_lo[tn][0] = __byte_perm(p0.x, p0.y, 0x5410);
                    b_lo[tn][1] = __byte_perm(p1.x, p1.y, 0x5410);
                }
                // 3-term split products
                #pragma unroll
                for (int tm = 0; tm < 2; tm++) {
                    #pragma unroll
                    for (int tn = 0; tn < 2; tn++) {
                        mma_bf16(d[tm][tn], a_hi[tm], b_hi[tn][0], b_hi[tn][1]);
                        mma_bf16(d[tm][tn], a_hi[tm], b_lo[tn][0], b_lo[tn][1]);
                        mma_bf16(d[tm][tn], a_lo[tm], b_hi[tn][0], b_hi[tn][1]);
                    }
                }
            }
        }

        // ---- activations, state update, h write (lane-local!) ----
        float hv[4];
        #pragma unroll
        for (int tn = 0; tn < 2; tn++) {
            #pragma unroll
            for (int j = 0; j < 2; j++) {
                const int idx = 2 * tn + j;
                const float ig = sigf(d[0][tn][j]);
                const float fg = sigf(d[0][tn][2 + j]);
                const float gg = tanh_fast(d[1][tn][j]);
                const float og = sigf(d[1][tn][2 + j]);
                const float cn = fmaf(fg, creg[idx], ig * gg);
                creg[idx] = cn;
                const float h = og * tanh_fast(cn);
                hv[idx] = h;
                const int b = bstart + w * 16 + tn * 8 + 2 * q + j;
                hnext[(size_t)b * Hn + colbase + cc] = packsplit(h);
            }
        }

        // ---- decoder output: y = h @ lin_W^T + lin_b ----
        if (!enc) {
            float py[4];
            #pragma unroll
            for (int idx = 0; idx < 4; idx++) py[idx] = hv[idx] * lw;
            // sum over the 8 col-lanes (lane bits 2..4)
            #pragma unroll
            for (int off = 4; off <= 16; off <<= 1) {
                #pragma unroll
                for (int idx = 0; idx < 4; idx++)
                    py[idx] += __shfl_xor_sync(0xffffffffu, py[idx], off);
            }
            if (cc == 0) {
                const float add = (gh == 0) ? lb : 0.0f;
                #pragma unroll
                for (int tn = 0; tn < 2; tn++)
                    #pragma unroll
                    for (int j = 0; j < 2; j++) {
                        const int b = bstart + w * 16 + tn * 8 + 2 * q + j;
                        atomicAdd(&out[(size_t)b * Pn + (s - Sn)],
                                  py[2 * tn + j] + add);
                    }
            }
        }

        grid_barrier();
    }
}

// ---------------- launch ----------------
extern "C" void kernel_launch(void* const* d_in, const int* in_sizes, int n_in,
                              void* d_out, int out_size)
{
    const float* x_enc   = (const float*)d_in[0];
    const float* enc_Wih = (const float*)d_in[1];
    const float* enc_Whh = (const float*)d_in[2];
    const float* enc_b   = (const float*)d_in[3];
    const float* dec_Wih = (const float*)d_in[4];
    const float* dec_Whh = (const float*)d_in[5];
    const float* dec_b   = (const float*)d_in[6];
    const float* lin_W   = (const float*)d_in[7];
    const float* lin_b   = (const float*)d_in[8];
    float* out = (float*)d_out;

    cudaFuncSetAttribute(lstm_kernel,
                         cudaFuncAttributeMaxDynamicSharedMemorySize, SMEM_BYTES);

    lstm_kernel<<<NBLK, 256, SMEM_BYTES>>>(x_enc, enc_Wih, enc_Whh, enc_b,
                                           dec_Wih, dec_Whh, dec_b,
                                           lin_W, lin_b, out);
}

// round 7
// speedup vs baseline: 2.6845x; 1.0405x over previous
#include <cuda_runtime.h>
#include <cuda_bf16.h>

// ---------------- problem dims ----------------
#define Bn 256
#define Sn 336
#define Fn 8
#define Hn 512
#define Pn 96

// ---------------- partition ----------------
#define GB   2                 // batch halves
#define GHN  64                // col groups
#define NBLK (GB * GHN)        // 128 blocks
#define BT   128               // batches per block
#define CT   8                 // cols per block
#define NR   32                // gate rows per block
#define KCH  128               // k elements per chunk
#define NCH  (Hn / KCH)        // 4

// plane strides in bf16 units; stride*2 mod 128 == 16 -> ldmatrix phases
// (8 rows) tile all 32 banks conflict-free
#define WPS 520                // W plane row stride (1040 B)
#define BPS 136                // h plane row stride (272 B)

#define W_HALF (NR * WPS)      // bf16 per W plane      = 16640
#define B_HALF (BT * BPS)      // bf16 per h plane/buf  = 17408
#define BF_TOTAL (2 * W_HALF + 4 * B_HALF)   // 102912 bf16 = 205824 B
#define XS_F   (BT * Fn)
#define SMEM_BYTES (BF_TOTAL * 2 + (XS_F + NR + NR * Fn) * 4)

// ---------------- device scratch: split bf16 planes of h ----------------
__device__ __nv_bfloat16 g_h_hi[2][Bn][Hn];
__device__ __nv_bfloat16 g_h_lo[2][Bn][Hn];
__device__ unsigned g_bar_count;
__device__ unsigned g_bar_gen;

// ---------------- helpers ----------------
__device__ __forceinline__ void cp_async16(void* dst_sh, const void* src) {
    unsigned d = (unsigned)__cvta_generic_to_shared(dst_sh);
    asm volatile("cp.async.ca.shared.global [%0], [%1], 16;\n" :: "r"(d), "l"(src));
}
__device__ __forceinline__ void cp_commit() {
    asm volatile("cp.async.commit_group;\n" ::: "memory");
}
template <int N>
__device__ __forceinline__ void cp_wait() {
    asm volatile("cp.async.wait_group %0;\n" :: "n"(N) : "memory");
}

__device__ __forceinline__ float sigf(float x) {
    return 1.0f / (1.0f + __expf(-x));
}
__device__ __forceinline__ float tanh_fast(float x) {
    return 2.0f / (1.0f + __expf(-2.0f * x)) - 1.0f;
}

// split fp32 into bf16 hi + bf16 lo (residual)
__device__ __forceinline__ void split2(float x, __nv_bfloat16& h, __nv_bfloat16& l) {
    h = __float2bfloat16(x);
    l = __float2bfloat16(x - __bfloat162float(h));
}

// m16n8k16 bf16 MMA, fp32 accumulate
__device__ __forceinline__ void mma_bf16(float d[4], const unsigned a[4],
                                         const unsigned b0, const unsigned b1) {
    asm volatile(
        "mma.sync.aligned.m16n8k16.row.col.f32.bf16.bf16.f32 "
        "{%0,%1,%2,%3},{%4,%5,%6,%7},{%8,%9},{%0,%1,%2,%3};"
        : "+f"(d[0]), "+f"(d[1]), "+f"(d[2]), "+f"(d[3])
        : "r"(a[0]), "r"(a[1]), "r"(a[2]), "r"(a[3]), "r"(b0), "r"(b1));
}

__device__ __forceinline__ void ldsm_x4(unsigned a[4], unsigned addr) {
    asm volatile("ldmatrix.sync.aligned.m8n8.x4.shared.b16 {%0,%1,%2,%3},[%4];"
                 : "=r"(a[0]), "=r"(a[1]), "=r"(a[2]), "=r"(a[3]) : "r"(addr));
}
__device__ __forceinline__ void ldsm_x2(unsigned b[2], unsigned addr) {
    asm volatile("ldmatrix.sync.aligned.m8n8.x2.shared.b16 {%0,%1},[%2];"
                 : "=r"(b[0]), "=r"(b[1]) : "r"(addr));
}

// grid-wide barrier, acquire/release
__device__ __forceinline__ void grid_barrier() {
    __syncthreads();
    if (threadIdx.x == 0) {
        unsigned gen;
        asm volatile("ld.acquire.gpu.u32 %0, [%1];"
                     : "=r"(gen) : "l"(&g_bar_gen) : "memory");
        unsigned prev;
        asm volatile("atom.add.release.gpu.u32 %0, [%1], 1;"
                     : "=r"(prev) : "l"(&g_bar_count) : "memory");
        if (prev == NBLK - 1) {
            asm volatile("st.relaxed.gpu.u32 [%0], %1;"
                         :: "l"(&g_bar_count), "r"(0u) : "memory");
            asm volatile("st.release.gpu.u32 [%0], %1;"
                         :: "l"(&g_bar_gen), "r"(gen + 1u) : "memory");
        } else {
            unsigned cur;
            do {
                asm volatile("ld.acquire.gpu.u32 %0, [%1];"
                             : "=r"(cur) : "l"(&g_bar_gen) : "memory");
            } while (cur == gen);
        }
    }
    __syncthreads();
}

// stage 32x512 weight slice split into hi/lo bf16 planes
__device__ __forceinline__ void stage_weights(__nv_bfloat16* Whi, __nv_bfloat16* Wlo,
                                              const float* W, int colbase, int tid) {
    const int r    = tid >> 3;      // 0..31
    const int seg  = tid & 7;       // 64-col segment
    const int gate = r >> 3;
    const int cc   = r & 7;
    const float* src = W + (size_t)(gate * Hn + colbase + cc) * Hn + seg * 64;
    __nv_bfloat16* dh = Whi + r * WPS + seg * 64;
    __nv_bfloat16* dl = Wlo + r * WPS + seg * 64;
    #pragma unroll
    for (int j = 0; j < 16; j++) {
        const float4 v = ((const float4*)src)[j];
        split2(v.x, dh[4 * j + 0], dl[4 * j + 0]);
        split2(v.y, dh[4 * j + 1], dl[4 * j + 1]);
        split2(v.z, dh[4 * j + 2], dl[4 * j + 2]);
        split2(v.w, dh[4 * j + 3], dl[4 * j + 3]);
    }
}

// ---------------- kernel ----------------
__global__ void __launch_bounds__(256, 1)
lstm_kernel(const float* __restrict__ x_enc,
            const float* __restrict__ enc_Wih,
            const float* __restrict__ enc_Whh,
            const float* __restrict__ enc_b,
            const float* __restrict__ dec_Wih,
            const float* __restrict__ dec_Whh,
            const float* __restrict__ dec_b,
            const float* __restrict__ lin_W,
            const float* __restrict__ lin_b,
            float* __restrict__ out)
{
    extern __shared__ __nv_bfloat16 smem_bf[];
    __nv_bfloat16* Whi = smem_bf;                  // [NR][WPS]
    __nv_bfloat16* Wlo = Whi + W_HALF;             // [NR][WPS]
    __nv_bfloat16* Bsh = Wlo + W_HALF;             // [2 buf][2 plane][BT][BPS]
    float* x_sh    = (float*)(smem_bf + BF_TOTAL); // [BT][Fn]
    float* bias_sh = x_sh + XS_F;                  // [NR]
    float* wih_sh  = bias_sh + NR;                 // [NR][Fn] (enc) / [NR] (dec)

    const int tid     = threadIdx.x;
    const int bid     = blockIdx.x;
    const int gh      = bid % GHN;
    const int gbx     = bid / GHN;
    const int bstart  = gbx * BT;
    const int colbase = gh * CT;

    const int w    = tid >> 5;      // warp 0..7 (batches w*16..w*16+15)
    const int lane = tid & 31;
    const int cc   = lane >> 2;     // frag group id (gate col / row)
    const int q    = lane & 3;      // frag thread-in-group

    // ---- stage encoder weights + bias + Wih ----
    stage_weights(Whi, Wlo, enc_Whh, colbase, tid);
    if (tid < NR) {
        const int g2 = tid >> 3, c2 = tid & 7;
        bias_sh[tid] = enc_b[g2 * Hn + colbase + c2];
        #pragma unroll
        for (int k = 0; k < Fn; k++)
            wih_sh[tid * Fn + k] = enc_Wih[(size_t)(g2 * Hn + colbase + c2) * Fn + k];
    }

    // ---- per-launch re-init of global scratch ----
    {
        const int per = (Bn * Hn) / NBLK;   // 1024
        __nv_bfloat16* zh = &g_h_hi[1][0][0] + bid * per;
        __nv_bfloat16* zl = &g_h_lo[1][0][0] + bid * per;
        for (int j = tid; j < per; j += 256) { zh[j] = __nv_bfloat16(0.f); zl[j] = __nv_bfloat16(0.f); }
        const int pero = (Bn * Pn + NBLK - 1) / NBLK;
        const int base = bid * pero;
        for (int j = tid; j < pero; j += 256)
            if (base + j < Bn * Pn) out[base + j] = 0.0f;
    }

    float creg[4] = {0.f, 0.f, 0.f, 0.f};
    const float lw = lin_W[colbase + cc];
    const float lb = lin_b[0];

    // ---- ldmatrix base addresses (byte, shared space) ----
    // A x4: matrix j = lane>>3: rows (j&1)*8 + (lane&7), k byte + (j>>1)*16
    unsigned aBase[2][2];   // [tm][plane]
    {
        const int mat  = lane >> 3;
        const int mrow = ((mat & 1) << 3) + (lane & 7);
        const int kb   = (mat >> 1) * 16;
        const unsigned whiA = (unsigned)__cvta_generic_to_shared(Whi);
        const unsigned wloA = (unsigned)__cvta_generic_to_shared(Wlo);
        #pragma unroll
        for (int tm = 0; tm < 2; tm++) {
            aBase[tm][0] = whiA + (unsigned)((16 * tm + mrow) * WPS) * 2 + kb;
            aBase[tm][1] = wloA + (unsigned)((16 * tm + mrow) * WPS) * 2 + kb;
        }
    }
    // B x2: matrix j = (lane&15)>>3: rows lane&7, k byte + j*16
    unsigned bBase[2][2];   // [tn][plane], buffer 0
    {
        const int l16  = lane & 15;
        const int nrow = l16 & 7;
        const int kb   = (l16 >> 3) * 16;
        const unsigned bA = (unsigned)__cvta_generic_to_shared(Bsh);
        #pragma unroll
        for (int tn = 0; tn < 2; tn++) {
            #pragma unroll
            for (int p = 0; p < 2; p++)
                bBase[tn][p] = bA + (unsigned)(p * B_HALF + (w * 16 + tn * 8 + nrow) * BPS) * 2 + kb;
        }
    }

    grid_barrier();   // scratch zeroed, weights staged

    float bias_r[4];
    #pragma unroll
    for (int g2 = 0; g2 < 4; g2++) bias_r[g2] = bias_sh[g2 * 8 + cc];

    for (int s = 0; s < Sn + Pn; s++) {
        const bool enc = (s < Sn);
        const __nv_bfloat16* hprev_hi = &g_h_hi[(s + 1) & 1][0][0];
        const __nv_bfloat16* hprev_lo = &g_h_lo[(s + 1) & 1][0][0];
        __nv_bfloat16*       hnext_hi = &g_h_hi[s & 1][0][0];
        __nv_bfloat16*       hnext_lo = &g_h_lo[s & 1][0][0];

        // ---- encoder -> decoder weight swap (once) ----
        if (s == Sn) {
            __syncthreads();
            stage_weights(Whi, Wlo, dec_Whh, colbase, tid);
            if (tid < NR) {
                const int g2 = tid >> 3, c2 = tid & 7;
                bias_sh[tid] = dec_b[g2 * Hn + colbase + c2];
                wih_sh[tid]  = dec_Wih[g2 * Hn + colbase + c2];
            }
            __syncthreads();
            #pragma unroll
            for (int g2 = 0; g2 < 4; g2++) bias_r[g2] = bias_sh[g2 * 8 + cc];
        }

        // ---- accumulator init: bias + Wih*x ----
        float d[2][2][4];
        if (enc) {
            {
                const int b = tid >> 1, part = tid & 1;
                const float4 v = *(const float4*)(x_enc +
                        ((size_t)(bstart + b) * Sn + s) * Fn + part * 4);
                *((float4*)&x_sh[b * Fn + part * 4]) = v;
            }
            __syncthreads();
            #pragma unroll
            for (int tn = 0; tn < 2; tn++) {
                #pragma unroll
                for (int j = 0; j < 2; j++) {
                    const int nb = w * 16 + tn * 8 + 2 * q + j;
                    float t[4];
                    #pragma unroll
                    for (int g2 = 0; g2 < 4; g2++) t[g2] = bias_r[g2];
                    #pragma unroll
                    for (int k = 0; k < Fn; k++) {
                        const float xv = x_sh[nb * Fn + k];
                        #pragma unroll
                        for (int g2 = 0; g2 < 4; g2++)
                            t[g2] = fmaf(xv, wih_sh[(g2 * 8 + cc) * Fn + k], t[g2]);
                    }
                    d[0][tn][0 + j] = t[0];
                    d[0][tn][2 + j] = t[1];
                    d[1][tn][0 + j] = t[2];
                    d[1][tn][2 + j] = t[3];
                }
            }
        } else {
            float wv[4];
            #pragma unroll
            for (int g2 = 0; g2 < 4; g2++) wv[g2] = wih_sh[g2 * 8 + cc];
            #pragma unroll
            for (int tn = 0; tn < 2; tn++) {
                #pragma unroll
                for (int j = 0; j < 2; j++) {
                    const int b = bstart + w * 16 + tn * 8 + 2 * q + j;
                    const float xv = (s == Sn)
                        ? x_enc[((size_t)b * Sn + (Sn - 1)) * Fn + 3]
                        : out[(size_t)b * Pn + (s - Sn - 1)];
                    d[0][tn][0 + j] = fmaf(xv, wv[0], bias_r[0]);
                    d[0][tn][2 + j] = fmaf(xv, wv[1], bias_r[1]);
                    d[1][tn][0 + j] = fmaf(xv, wv[2], bias_r[2]);
                    d[1][tn][2 + j] = fmaf(xv, wv[3], bias_r[3]);
                }
            }
        }

        // ---- GEMM over K=512, cp.async double-buffered hi/lo h planes ----
        {   // prefetch chunk 0: 2 planes x 128 rows x 16 x 16B
            #pragma unroll
            for (int j = 0; j < 16; j++) {
                const int idx   = j * 256 + tid;
                const int plane = idx >> 11;
                const int rem   = idx & 2047;
                const int row   = rem >> 4;
                const int seg   = rem & 15;
                const __nv_bfloat16* sp = plane ? hprev_lo : hprev_hi;
                cp_async16(Bsh + plane * B_HALF + row * BPS + seg * 8,
                           sp + (size_t)(bstart + row) * Hn + seg * 8);
            }
            cp_commit();
        }

        for (int ci = 0; ci < NCH; ci++) {
            __syncthreads();
            if (ci + 1 < NCH) {
                __nv_bfloat16* dst = Bsh + ((ci + 1) & 1) * (2 * B_HALF);
                const int koff = (ci + 1) * KCH;
                #pragma unroll
                for (int j = 0; j < 16; j++) {
                    const int idx   = j * 256 + tid;
                    const int plane = idx >> 11;
                    const int rem   = idx & 2047;
                    const int row   = rem >> 4;
                    const int seg   = rem & 15;
                    const __nv_bfloat16* sp = plane ? hprev_lo : hprev_hi;
                    cp_async16(dst + plane * B_HALF + row * BPS + seg * 8,
                               sp + (size_t)(bstart + row) * Hn + koff + seg * 8);
                }
                cp_commit();
                cp_wait<1>();
            } else {
                cp_wait<0>();
            }
            __syncthreads();

            const unsigned bufOff = (unsigned)((ci & 1) * (2 * B_HALF)) * 2;
            #pragma unroll
            for (int kt = 0; kt < KCH / 16; kt++) {
                const unsigned kbA = (unsigned)(ci * KCH + kt * 16) * 2;  // bytes
                const unsigned kbB = bufOff + (unsigned)(kt * 16) * 2;

                unsigned a_hi[2][4], a_lo[2][4];
                #pragma unroll
                for (int tm = 0; tm < 2; tm++) {
                    ldsm_x4(a_hi[tm], aBase[tm][0] + kbA);
                    ldsm_x4(a_lo[tm], aBase[tm][1] + kbA);
                }
                unsigned b_hi[2][2], b_lo[2][2];
                #pragma unroll
                for (int tn = 0; tn < 2; tn++) {
                    ldsm_x2(b_hi[tn], bBase[tn][0] + kbB);
                    ldsm_x2(b_lo[tn], bBase[tn][1] + kbB);
                }
                #pragma unroll
                for (int tm = 0; tm < 2; tm++) {
                    #pragma unroll
                    for (int tn = 0; tn < 2; tn++) {
                        mma_bf16(d[tm][tn], a_hi[tm], b_hi[tn][0], b_hi[tn][1]);
                        mma_bf16(d[tm][tn], a_hi[tm], b_lo[tn][0], b_lo[tn][1]);
                        mma_bf16(d[tm][tn], a_lo[tm], b_hi[tn][0], b_hi[tn][1]);
                    }
                }
            }
        }

        // ---- activations, state update, h write (lane-local) ----
        float hv[4];
        #pragma unroll
        for (int tn = 0; tn < 2; tn++) {
            #pragma unroll
            for (int j = 0; j < 2; j++) {
                const int idx = 2 * tn + j;
                const float ig = sigf(d[0][tn][j]);
                const float fg = sigf(d[0][tn][2 + j]);
                const float gg = tanh_fast(d[1][tn][j]);
                const float og = sigf(d[1][tn][2 + j]);
                const float cn = fmaf(fg, creg[idx], ig * gg);
                creg[idx] = cn;
                const float h = og * tanh_fast(cn);
                hv[idx] = h;
                const int b = bstart + w * 16 + tn * 8 + 2 * q + j;
                __nv_bfloat16 hh, hl;
                split2(h, hh, hl);
                hnext_hi[(size_t)b * Hn + colbase + cc] = hh;
                hnext_lo[(size_t)b * Hn + colbase + cc] = hl;
            }
        }

        // ---- decoder output: y = h @ lin_W^T + lin_b ----
        if (!enc) {
            float py[4];
            #pragma unroll
            for (int idx = 0; idx < 4; idx++) py[idx] = hv[idx] * lw;
            #pragma unroll
            for (int off = 4; off <= 16; off <<= 1) {
                #pragma unroll
                for (int idx = 0; idx < 4; idx++)
                    py[idx] += __shfl_xor_sync(0xffffffffu, py[idx], off);
            }
            if (cc == 0) {
                const float add = (gh == 0) ? lb : 0.0f;
                #pragma unroll
                for (int tn = 0; tn < 2; tn++)
                    #pragma unroll
                    for (int j = 0; j < 2; j++) {
                        const int b = bstart + w * 16 + tn * 8 + 2 * q + j;
                        atomicAdd(&out[(size_t)b * Pn + (s - Sn)],
                                  py[2 * tn + j] + add);
                    }
            }
        }

        grid_barrier();
    }
}

// ---------------- launch ----------------
extern "C" void kernel_launch(void* const* d_in, const int* in_sizes, int n_in,
                              void* d_out, int out_size)
{
    const float* x_enc   = (const float*)d_in[0];
    const float* enc_Wih = (const float*)d_in[1];
    const float* enc_Whh = (const float*)d_in[2];
    const float* enc_b   = (const float*)d_in[3];
    const float* dec_Wih = (const float*)d_in[4];
    const float* dec_Whh = (const float*)d_in[5];
    const float* dec_b   = (const float*)d_in[6];
    const float* lin_W   = (const float*)d_in[7];
    const float* lin_b   = (const float*)d_in[8];
    float* out = (float*)d_out;

    cudaFuncSetAttribute(lstm_kernel,
                         cudaFuncAttributeMaxDynamicSharedMemorySize, SMEM_BYTES);

    lstm_kernel<<<NBLK, 256, SMEM_BYTES>>>(x_enc, enc_Wih, enc_Whh, enc_b,
                                           dec_Wih, dec_Whh, dec_b,
                                           lin_W, lin_b, out);
}